// round 8
// baseline (speedup 1.0000x reference)
#include <cuda_runtime.h>
#include <cuda_bf16.h>
#include <math.h>
#include <stdint.h>

#define BB    8
#define CIN   256
#define OUTC  256
#define SHAREC 8
#define GG    32
#define MID   320
#define MIDP  384
#define WOUT  288
#define P     4096

// ---------------- scratch (static device arrays; no allocation) ----------------
__device__ float g_y[(size_t)BB * MID * P];      // conv1x1 outputs [b][c][p]
__device__ float g_t[(size_t)BB * GG * P];       // weight-gen hidden
__device__ float g_bias[MIDP];
__device__ float g_bn1s[MID];
__device__ float g_bn1b[MID];
__device__ float g_bn2s[GG];
__device__ float g_bn2b[GG];
__device__ __nv_bfloat16 g_whi[MIDP * CIN];      // conv weights hi/lo, [m][k]
__device__ __nv_bfloat16 g_wlo[MIDP * CIN];
__device__ __nv_bfloat16 g_c1hi[GG * MID];       // cw1 hi/lo, [g][k]
__device__ __nv_bfloat16 g_c1lo[GG * MID];

__device__ __forceinline__ uint32_t smem_u32(const void* p) {
    uint32_t a;
    asm("{ .reg .u64 t; cvta.to.shared.u64 t, %1; cvt.u32.u64 %0, t; }" : "=r"(a) : "l"(p));
    return a;
}

#define LDSM4(r0, r1, r2, r3, addr) \
    asm volatile("ldmatrix.sync.aligned.m8n8.x4.shared.b16 {%0,%1,%2,%3}, [%4];" \
        : "=r"(r0), "=r"(r1), "=r"(r2), "=r"(r3) : "r"(addr))

#define MMA_BF16(d, a, b) \
    asm volatile("mma.sync.aligned.m16n8k16.row.col.f32.bf16.bf16.f32 " \
        "{%0,%1,%2,%3}, {%4,%5,%6,%7}, {%8,%9}, {%0,%1,%2,%3};" \
        : "+f"((d)[0]), "+f"((d)[1]), "+f"((d)[2]), "+f"((d)[3]) \
        : "r"((a)[0]), "r"((a)[1]), "r"((a)[2]), "r"((a)[3]), "r"((b)[0]), "r"((b)[1]))

#define CP_ASYNC16(saddr, gptr) \
    asm volatile("cp.async.cg.shared.global [%0], [%1], 16;" :: "r"(saddr), "l"(gptr))
#define CP_COMMIT() asm volatile("cp.async.commit_group;" ::: "memory")
#define CP_WAIT0()  asm volatile("cp.async.wait_group 0;" ::: "memory")

// ---------------- K0a: pack + split weights (fully parallel, coalesced) ----------------
__global__ __launch_bounds__(256) void packw_kernel(const float* __restrict__ w1,
                                                    const float* __restrict__ w2,
                                                    const float* __restrict__ w3,
                                                    const float* __restrict__ cw1) {
    int idx = blockIdx.x * 256 + threadIdx.x;
    if (idx < MIDP * CIN) {
        int c = idx >> 8;
        int k = idx & 255;
        float v = 0.f;
        if (c < 32)       v = w1[c * CIN + k];
        else if (c < 64)  v = w2[(c - 32) * CIN + k];
        else if (c < MID) v = w3[(c - 64) * CIN + k];
        __nv_bfloat16 hi = __float2bfloat16(v);
        g_whi[idx] = hi;
        g_wlo[idx] = __float2bfloat16(v - __bfloat162float(hi));
    } else {
        int j = idx - MIDP * CIN;
        if (j < GG * MID) {
            float v = cw1[j];
            __nv_bfloat16 hi = __float2bfloat16(v);
            g_c1hi[j] = hi;
            g_c1lo[j] = __float2bfloat16(v - __bfloat162float(hi));
        }
    }
}

// ---------------- K0a': fold BN params + biases ----------------
__global__ void packbn_kernel(const float* __restrict__ b1, const float* __restrict__ b2,
                              const float* __restrict__ b3,
                              const float* __restrict__ bn1_g, const float* __restrict__ bn1_b,
                              const float* __restrict__ bn1_m, const float* __restrict__ bn1_v,
                              const float* __restrict__ bn2_g, const float* __restrict__ bn2_b,
                              const float* __restrict__ bn2_m, const float* __restrict__ bn2_v) {
    int c = blockIdx.x * 128 + threadIdx.x;
    if (c >= MID) return;
    g_bias[c] = (c < 32) ? b1[c] : (c < 64) ? b2[c - 32] : b3[c - 64];
    float s = bn1_g[c] * rsqrtf(bn1_v[c] + 1e-5f);
    g_bn1s[c] = s;
    g_bn1b[c] = bn1_b[c] - bn1_m[c] * s;
    if (c < GG) {
        float s2 = bn2_g[c] * rsqrtf(bn2_v[c] + 1e-5f);
        g_bn2s[c] = s2;
        g_bn2b[c] = bn2_b[c] - bn2_m[c] * s2;
    }
}

// ---------------- K1: conv1x1 split-bf16 GEMM with fused x transpose/convert ----------------
// CTA: 128 M x 128 N(pixels), K=256 in 4 chunks of 64.
// A (weights, bf16 hi/lo) cp.async double-buffered; x raw fp32 [k][p] staged via cp.async,
// converted in-kernel to swizzled [p][k] bf16 hi/lo B tiles (identical layout to R7).
#define CA_HI(s)  ((s) * 32768)
#define CA_LO(s)  ((s) * 32768 + 16384)
#define CX(s)     (65536 + (s) * 32768)        // fp32 staging: 64 rows x 512B
#define CBHI      131072
#define CBLO      147456
#define SM_TOTAL  163840

__global__ __launch_bounds__(256) void conv_mma_kernel(const float* __restrict__ x) {
    extern __shared__ char smem[];
    const uint32_t sbase = smem_u32(smem);
    const int tid = threadIdx.x;
    const int wid = tid >> 5;
    const int lid = tid & 31;
    const int b  = blockIdx.z;
    const int m0 = blockIdx.y * 128;
    const int p0 = blockIdx.x * 128;
    const int wm = wid & 3;
    const int wn = wid >> 2;

    float acc[2][8][4];
#pragma unroll
    for (int i = 0; i < 2; i++)
#pragma unroll
        for (int j = 0; j < 8; j++)
#pragma unroll
            for (int q = 0; q < 4; q++) acc[i][j][q] = 0.f;

    const int rowA[2] = { wm * 32 + (lid & 15), wm * 32 + 16 + (lid & 15) };
    const int c16A = (lid >> 4) * 16;
    int rowB[4];
#pragma unroll
    for (int nfp = 0; nfp < 4; nfp++)
        rowB[nfp] = wn * 64 + nfp * 16 + ((lid >> 4) * 8) + (lid & 7);
    const int c16B = ((lid >> 3) & 1) * 16;

    // A loader mapping: 128 rows x 64 k (128B rows), 4 rows per thread
    const int rowL = tid >> 3;
    const int ccL  = (tid & 7) * 16;
    uint32_t ldstA[4];
    const __nv_bfloat16 *srcAh[4], *srcAl[4];
#pragma unroll
    for (int e = 0; e < 4; e++) {
        int row = rowL + e * 32;
        ldstA[e] = (uint32_t)(row * 128) + (uint32_t)(ccL ^ ((row & 7) * 16));
        size_t sA = (size_t)(m0 + row) * CIN + (ccL >> 1);
        srcAh[e] = &g_whi[sA]; srcAl[e] = &g_wlo[sA];
    }
    // X loader mapping: 64 rows x 512B = 2048 x 16B chunks, 8 per thread
    const float* xbase = x + (size_t)b * CIN * P + p0;

    auto issue = [&](int c, int s) {
        const uint32_t stb = sbase + (uint32_t)(s * 32768);
        const int koff = c * 64;
#pragma unroll
        for (int e = 0; e < 4; e++) {
            CP_ASYNC16(stb + ldstA[e], srcAh[e] + koff);
            CP_ASYNC16(stb + 16384 + ldstA[e], srcAl[e] + koff);
        }
        const uint32_t xstb = sbase + (uint32_t)CX(s);
#pragma unroll
        for (int e = 0; e < 8; e++) {
            int id = e * 256 + tid;
            int kx = id >> 5, ux = id & 31;
            CP_ASYNC16(xstb + (uint32_t)(kx * 512 + ux * 16),
                       xbase + (size_t)(koff + kx) * P + ux * 4);
        }
        CP_COMMIT();
    };

    // convert-thread mapping: p = tid&127, k-half = (tid>>7)*32
    const int cvp = tid & 127;
    const int cvk = (tid >> 7) * 32;

    issue(0, 0);
    for (int c = 0; c < 4; c++) {
        CP_WAIT0();
        __syncthreads();    // chunk c data visible; chunk c-1 readers retired

        // ---- convert fp32 staging -> swizzled bf16 hi/lo B tile ----
        {
            const char* xs = smem + CX(c & 1);
#pragma unroll
            for (int e = 0; e < 16; e++) {
                int k = cvk + 2 * e;
                float f0 = *(const float*)(xs + k * 512 + cvp * 4);
                float f1 = *(const float*)(xs + (k + 1) * 512 + cvp * 4);
                __nv_bfloat16 h0 = __float2bfloat16(f0);
                __nv_bfloat16 h1 = __float2bfloat16(f1);
                __nv_bfloat16 l0 = __float2bfloat16(f0 - __bfloat162float(h0));
                __nv_bfloat16 l1 = __float2bfloat16(f1 - __bfloat162float(h1));
                uint32_t d = (uint32_t)(cvp * 128) + (uint32_t)((2 * k) ^ ((cvp & 7) * 16));
                *(__nv_bfloat162*)(smem + CBHI + d) = __nv_bfloat162(h0, h1);
                *(__nv_bfloat162*)(smem + CBLO + d) = __nv_bfloat162(l0, l1);
            }
        }
        if (c < 3) issue(c + 1, (c + 1) & 1);
        __syncthreads();    // B tile ready

        const uint32_t astb = sbase + (uint32_t)((c & 1) * 32768);
#pragma unroll
        for (int ks = 0; ks < 4; ks++) {
            const int colA = (ks * 32 + c16A);
            const int colB = (ks * 32 + c16B);
            uint32_t ah[2][4], al[2][4];
#pragma unroll
            for (int mf = 0; mf < 2; mf++) {
                uint32_t off = (uint32_t)(rowA[mf] * 128) +
                               (uint32_t)(colA ^ ((rowA[mf] & 7) * 16));
                LDSM4(ah[mf][0], ah[mf][1], ah[mf][2], ah[mf][3], astb + off);
                LDSM4(al[mf][0], al[mf][1], al[mf][2], al[mf][3], astb + 16384 + off);
            }
            uint32_t bh[8][2], bl[8][2];
#pragma unroll
            for (int nfp = 0; nfp < 4; nfp++) {
                uint32_t off = (uint32_t)(rowB[nfp] * 128) +
                               (uint32_t)(colB ^ ((rowB[nfp] & 7) * 16));
                LDSM4(bh[2 * nfp][0], bh[2 * nfp][1], bh[2 * nfp + 1][0], bh[2 * nfp + 1][1],
                      sbase + CBHI + off);
                LDSM4(bl[2 * nfp][0], bl[2 * nfp][1], bl[2 * nfp + 1][0], bl[2 * nfp + 1][1],
                      sbase + CBLO + off);
            }
#pragma unroll
            for (int mf = 0; mf < 2; mf++)
#pragma unroll
                for (int nf = 0; nf < 8; nf++) {
                    MMA_BF16(acc[mf][nf], ah[mf], bh[nf]);
                    MMA_BF16(acc[mf][nf], ah[mf], bl[nf]);
                    MMA_BF16(acc[mf][nf], al[mf], bh[nf]);
                }
        }
    }

    const int r = lid >> 2;
    const int cc = (lid & 3) * 2;
#pragma unroll
    for (int mf = 0; mf < 2; mf++) {
        int m1 = m0 + wm * 32 + mf * 16 + r;
        int m2 = m1 + 8;
        float bv1 = (m1 < MID) ? g_bias[m1] : 0.f;
        float bv2 = (m2 < MID) ? g_bias[m2] : 0.f;
#pragma unroll
        for (int nf = 0; nf < 8; nf++) {
            int p = p0 + wn * 64 + nf * 8 + cc;
            if (m1 < MID) {
                float2 v = make_float2(acc[mf][nf][0] + bv1, acc[mf][nf][1] + bv1);
                *(float2*)&g_y[((size_t)b * MID + m1) * P + p] = v;
            }
            if (m2 < MID) {
                float2 v = make_float2(acc[mf][nf][2] + bv2, acc[mf][nf][3] + bv2);
                *(float2*)&g_y[((size_t)b * MID + m2) * P + p] = v;
            }
        }
    }
}

// ---------------- K3: wgen1 via mma.sync with fused reflect-unfold gather (proven) ----------------
#define W1_AH   0
#define W1_AL   20480
#define W1_BH   40960
#define W1_BL   57344
#define W1_C4   73728
#define W1_CB   (W1_C4 + 320 * 16)
#define W1_TOTAL (W1_CB + 320 * 4)

__global__ __launch_bounds__(256) void wgen1_mma_kernel() {
    extern __shared__ char smem[];
    const uint32_t sbase = smem_u32(smem);
    int4*  s_c4 = (int4*)(smem + W1_C4);
    float* s_cb = (float*)(smem + W1_CB);
    const int tid = threadIdx.x;
    const int wid = tid >> 5;
    const int lid = tid & 31;
    const int b  = blockIdx.y;
    const int p0 = blockIdx.x * 128;
    const float* yb = g_y + (size_t)b * MID * P;

#pragma unroll
    for (int e = 0; e < 5; e++) {
        int idx = tid + e * 256;
        int c = idx >> 8, rem = idx & 255;
        int m = rem >> 3, kg = rem & 7;
        uint32_t dst = (uint32_t)(c * 4096 + m * 128) + (uint32_t)((kg * 16) ^ ((m & 7) * 16));
        size_t src = (size_t)m * MID + c * 64 + kg * 8;
        *(uint4*)(smem + W1_AH + dst) = *(const uint4*)&g_c1hi[src];
        *(uint4*)(smem + W1_AL + dst) = *(const uint4*)&g_c1lo[src];
    }
    for (int k = tid; k < MID; k += 256) {
        int ch, di, dj;
        if (k < 32) { ch = k; di = 0; dj = 0; }
        else {
            int cc = k - 32;
            int rr = cc / 9, t9 = cc - rr * 9;
            ch = 32 + rr;
            di = t9 / 3 - 1;
            dj = t9 - (t9 / 3) * 3 - 1;
        }
        s_c4[k] = make_int4(ch, di, dj, __float_as_int(g_bn1s[k]));
        s_cb[k] = g_bn1b[k];
    }
    __syncthreads();

    float acc[2][2][4];
#pragma unroll
    for (int i = 0; i < 2; i++)
#pragma unroll
        for (int j = 0; j < 2; j++)
#pragma unroll
            for (int q = 0; q < 4; q++) acc[i][j][q] = 0.f;

    const int rowA[2] = { (lid & 15), 16 + (lid & 15) };
    const int c16A = (lid >> 4) * 16;
    const int rowB = wid * 16 + ((lid >> 4) * 8) + (lid & 7);
    const int c16B = ((lid >> 3) & 1) * 16;

    const int fpx = tid & 127;
    const int fkh = (tid >> 7) * 32;
    const int pi = (p0 + fpx) >> 6;
    const int pj = (p0 + fpx) & 63;

    for (int c = 0; c < 5; c++) {
        const int kk = c * 64;
#pragma unroll
        for (int e = 0; e < 16; e++) {
            int kloc0 = fkh + 2 * e;
            int k0 = kk + kloc0;
            int4 c40 = s_c4[k0];
            int4 c41 = s_c4[k0 + 1];
            float b0 = s_cb[k0], b1 = s_cb[k0 + 1];
            int i0 = pi + c40.y, j0 = pj + c40.z;
            i0 = min(abs(i0), 126 - i0); j0 = min(abs(j0), 126 - j0);
            int i1 = pi + c41.y, j1 = pj + c41.z;
            i1 = min(abs(i1), 126 - i1); j1 = min(abs(j1), 126 - j1);
            float v0 = yb[(size_t)c40.x * P + (i0 << 6) + j0];
            float v1 = yb[(size_t)c41.x * P + (i1 << 6) + j1];
            float h0 = fmaxf(fmaf(v0, __int_as_float(c40.w), b0), 0.f);
            float h1 = fmaxf(fmaf(v1, __int_as_float(c41.w), b1), 0.f);
            __nv_bfloat16 hh0 = __float2bfloat16(h0);
            __nv_bfloat16 hh1 = __float2bfloat16(h1);
            __nv_bfloat16 ll0 = __float2bfloat16(h0 - __bfloat162float(hh0));
            __nv_bfloat16 ll1 = __float2bfloat16(h1 - __bfloat162float(hh1));
            uint32_t dst = (uint32_t)(fpx * 128) + (uint32_t)((kloc0 * 2) ^ ((fpx & 7) * 16));
            *(__nv_bfloat162*)(smem + W1_BH + dst) = __nv_bfloat162(hh0, hh1);
            *(__nv_bfloat162*)(smem + W1_BL + dst) = __nv_bfloat162(ll0, ll1);
        }
        __syncthreads();

        const uint32_t abase = (uint32_t)(c * 4096);
#pragma unroll
        for (int ks = 0; ks < 4; ks++) {
            const int colA = ks * 32 + c16A;
            const int colB = ks * 32 + c16B;
            uint32_t ah[2][4], al[2][4];
#pragma unroll
            for (int mf = 0; mf < 2; mf++) {
                uint32_t off = abase + (uint32_t)(rowA[mf] * 128) +
                               (uint32_t)(colA ^ ((rowA[mf] & 7) * 16));
                LDSM4(ah[mf][0], ah[mf][1], ah[mf][2], ah[mf][3], sbase + W1_AH + off);
                LDSM4(al[mf][0], al[mf][1], al[mf][2], al[mf][3], sbase + W1_AL + off);
            }
            uint32_t bh[2][2], bl[2][2];
            {
                uint32_t off = (uint32_t)(rowB * 128) + (uint32_t)(colB ^ ((rowB & 7) * 16));
                LDSM4(bh[0][0], bh[0][1], bh[1][0], bh[1][1], sbase + W1_BH + off);
                LDSM4(bl[0][0], bl[0][1], bl[1][0], bl[1][1], sbase + W1_BL + off);
            }
#pragma unroll
            for (int mf = 0; mf < 2; mf++)
#pragma unroll
                for (int nf = 0; nf < 2; nf++) {
                    MMA_BF16(acc[mf][nf], ah[mf], bh[nf]);
                    MMA_BF16(acc[mf][nf], ah[mf], bl[nf]);
                    MMA_BF16(acc[mf][nf], al[mf], bh[nf]);
                }
        }
        __syncthreads();
    }

    const int r = lid >> 2;
    const int c2 = (lid & 3) * 2;
#pragma unroll
    for (int mf = 0; mf < 2; mf++) {
        int g1 = mf * 16 + r;
        int g2 = g1 + 8;
        float s1 = g_bn2s[g1], sb1 = g_bn2b[g1];
        float s2 = g_bn2s[g2], sb2 = g_bn2b[g2];
#pragma unroll
        for (int nf = 0; nf < 2; nf++) {
            int p = p0 + wid * 16 + nf * 8 + c2;
            float2 v1 = make_float2(fmaxf(fmaf(acc[mf][nf][0], s1, sb1), 0.f),
                                    fmaxf(fmaf(acc[mf][nf][1], s1, sb1), 0.f));
            *(float2*)&g_t[((size_t)b * GG + g1) * P + p] = v1;
            float2 v2 = make_float2(fmaxf(fmaf(acc[mf][nf][2], s2, sb2), 0.f),
                                    fmaxf(fmaf(acc[mf][nf][3], s2, sb2), 0.f));
            *(float2*)&g_t[((size_t)b * GG + g2) * P + p] = v2;
        }
    }
}

// ---------------- K4+K5 fused: per-pixel weight gen + local grouped 3x3 conv ----------------
__global__ __launch_bounds__(256) void wgen2_local_kernel(const float* __restrict__ cw2,
                                                          const float* __restrict__ cb2,
                                                          float* __restrict__ out) {
    __shared__ float ts[GG][64];
    __shared__ float w2s[WOUT * GG];
    __shared__ float cbs[WOUT];
    const int b  = blockIdx.y;
    const int p0 = blockIdx.x * 64;
    const int tid = threadIdx.x;

#pragma unroll
    for (int e = 0; e < 8; e++) {
        int idx = tid + e * 256;
        int g = idx >> 6, n = idx & 63;
        ts[g][n] = g_t[((size_t)b * GG + g) * P + p0 + n];
    }
    for (int idx = tid; idx < WOUT * GG; idx += 256) w2s[idx] = cw2[idx];
    for (int idx = tid; idx < WOUT; idx += 256) cbs[idx] = cb2[idx];
    __syncthreads();

    const int pp = tid & 63;
    const int q  = tid >> 6;
    const int i  = blockIdx.x;
    const int j  = pp;

    float tv[GG];
#pragma unroll
    for (int g = 0; g < GG; g++) tv[g] = ts[g][pp];

#pragma unroll
    for (int g8 = 0; g8 < 8; g8++) {
        const int g = q * 8 + g8;
        float w[9];
#pragma unroll
        for (int t9 = 0; t9 < 9; t9++) {
            float acc = cbs[g * 9 + t9];
            const float4* wrow = (const float4*)&w2s[(g * 9 + t9) * GG];
#pragma unroll
            for (int k4 = 0; k4 < 8; k4++) {
                float4 wv = wrow[k4];
                acc += wv.x * tv[4 * k4] + wv.y * tv[4 * k4 + 1]
                     + wv.z * tv[4 * k4 + 2] + wv.w * tv[4 * k4 + 3];
            }
            w[t9] = acc;
        }
        const float* x3 = g_y + ((size_t)b * MID + 64 + g * SHAREC) * P;
        float* ob = out + ((size_t)b * OUTC + g * SHAREC) * P + p0 + pp;
#pragma unroll
        for (int s = 0; s < SHAREC; s++) {
            const float* xc = x3 + (size_t)s * P;
            float acc = 0.f;
#pragma unroll
            for (int ki = 0; ki < 3; ki++) {
                int ii = i + ki - 1;
                if (ii < 0 || ii > 63) continue;
#pragma unroll
                for (int kj = 0; kj < 3; kj++) {
                    int jj = j + kj - 1;
                    if (jj < 0 || jj > 63) continue;
                    acc += xc[(ii << 6) + jj] * w[ki * 3 + kj];
                }
            }
            ob[(size_t)s * P] = acc;
        }
    }
}

// ---------------- launch ----------------
extern "C" void kernel_launch(void* const* d_in, const int* in_sizes, int n_in,
                              void* d_out, int out_size) {
    const float* x     = (const float*)d_in[0];
    const float* w1    = (const float*)d_in[1];
    const float* b1    = (const float*)d_in[2];
    const float* w2    = (const float*)d_in[3];
    const float* b2    = (const float*)d_in[4];
    const float* w3    = (const float*)d_in[5];
    const float* b3    = (const float*)d_in[6];
    const float* bn1_g = (const float*)d_in[7];
    const float* bn1_b = (const float*)d_in[8];
    const float* bn1_m = (const float*)d_in[9];
    const float* bn1_v = (const float*)d_in[10];
    const float* cw1   = (const float*)d_in[11];
    const float* bn2_g = (const float*)d_in[12];
    const float* bn2_b = (const float*)d_in[13];
    const float* bn2_m = (const float*)d_in[14];
    const float* bn2_v = (const float*)d_in[15];
    const float* cw2   = (const float*)d_in[16];
    const float* cb2   = (const float*)d_in[17];
    float* out = (float*)d_out;

    static int smem_set = 0;
    if (!smem_set) {
        cudaFuncSetAttribute(conv_mma_kernel,
                             cudaFuncAttributeMaxDynamicSharedMemorySize, SM_TOTAL);
        cudaFuncSetAttribute(wgen1_mma_kernel,
                             cudaFuncAttributeMaxDynamicSharedMemorySize, W1_TOTAL);
        smem_set = 1;
    }

    packw_kernel<<<(MIDP * CIN + GG * MID + 255) / 256, 256>>>(w1, w2, w3, cw1);
    packbn_kernel<<<3, 128>>>(b1, b2, b3,
                              bn1_g, bn1_b, bn1_m, bn1_v,
                              bn2_g, bn2_b, bn2_m, bn2_v);
    {
        dim3 grid(P / 128, MIDP / 128, BB);   // 32 x 3 x 8
        conv_mma_kernel<<<grid, 256, SM_TOTAL>>>(x);
    }
    {
        dim3 grid(P / 128, BB);               // 32 x 8
        wgen1_mma_kernel<<<grid, 256, W1_TOTAL>>>();
    }
    {
        dim3 grid(P / 64, BB);                // 64 x 8
        wgen2_local_kernel<<<grid, 256>>>(cw2, cb2, out);
    }
}

// round 9
// speedup vs baseline: 1.0156x; 1.0156x over previous
#include <cuda_runtime.h>
#include <cuda_bf16.h>
#include <math.h>
#include <stdint.h>

#define BB    8
#define CIN   256
#define OUTC  256
#define SHAREC 8
#define GG    32
#define MID   320
#define MIDP  384
#define WOUT  288
#define P     4096

// ---------------- scratch (static device arrays; no allocation) ----------------
__device__ float g_y[(size_t)BB * MID * P];      // conv1x1 outputs [b][c][p]
__device__ float g_t[(size_t)BB * GG * P];       // weight-gen hidden
__device__ float g_bias[MIDP];
__device__ float g_bn1s[MID];
__device__ float g_bn1b[MID];
__device__ float g_bn2s[GG];
__device__ float g_bn2b[GG];
__device__ __nv_bfloat16 g_whi[MIDP * CIN];      // conv weights hi/lo, [m][k]
__device__ __nv_bfloat16 g_wlo[MIDP * CIN];
__device__ __nv_bfloat16 g_xhi[(size_t)BB * P * CIN];  // x transposed: [b][p][c]
__device__ __nv_bfloat16 g_xlo[(size_t)BB * P * CIN];
__device__ __nv_bfloat16 g_c1hi[GG * MID];       // cw1 hi/lo, [g][k]
__device__ __nv_bfloat16 g_c1lo[GG * MID];

__device__ __forceinline__ uint32_t smem_u32(const void* p) {
    uint32_t a;
    asm("{ .reg .u64 t; cvta.to.shared.u64 t, %1; cvt.u32.u64 %0, t; }" : "=r"(a) : "l"(p));
    return a;
}

#define LDSM4(r0, r1, r2, r3, addr) \
    asm volatile("ldmatrix.sync.aligned.m8n8.x4.shared.b16 {%0,%1,%2,%3}, [%4];" \
        : "=r"(r0), "=r"(r1), "=r"(r2), "=r"(r3) : "r"(addr))

#define MMA_BF16(d, a, b) \
    asm volatile("mma.sync.aligned.m16n8k16.row.col.f32.bf16.bf16.f32 " \
        "{%0,%1,%2,%3}, {%4,%5,%6,%7}, {%8,%9}, {%0,%1,%2,%3};" \
        : "+f"((d)[0]), "+f"((d)[1]), "+f"((d)[2]), "+f"((d)[3]) \
        : "r"((a)[0]), "r"((a)[1]), "r"((a)[2]), "r"((a)[3]), "r"((b)[0]), "r"((b)[1]))

#define CP_ASYNC16(saddr, gptr) \
    asm volatile("cp.async.cg.shared.global [%0], [%1], 16;" :: "r"(saddr), "l"(gptr))
#define CP_COMMIT() asm volatile("cp.async.commit_group;" ::: "memory")
#define CP_WAIT1()  asm volatile("cp.async.wait_group 1;" ::: "memory")
#define CP_WAIT0()  asm volatile("cp.async.wait_group 0;" ::: "memory")

// ---------------- K0a: pack + split weights ----------------
__global__ __launch_bounds__(256) void packw_kernel(const float* __restrict__ w1,
                                                    const float* __restrict__ w2,
                                                    const float* __restrict__ w3,
                                                    const float* __restrict__ cw1) {
    int idx = blockIdx.x * 256 + threadIdx.x;
    if (idx < MIDP * CIN) {
        int c = idx >> 8;
        int k = idx & 255;
        float v = 0.f;
        if (c < 32)       v = w1[c * CIN + k];
        else if (c < 64)  v = w2[(c - 32) * CIN + k];
        else if (c < MID) v = w3[(c - 64) * CIN + k];
        __nv_bfloat16 hi = __float2bfloat16(v);
        g_whi[idx] = hi;
        g_wlo[idx] = __float2bfloat16(v - __bfloat162float(hi));
    } else {
        int j = idx - MIDP * CIN;
        if (j < GG * MID) {
            float v = cw1[j];
            __nv_bfloat16 hi = __float2bfloat16(v);
            g_c1hi[j] = hi;
            g_c1lo[j] = __float2bfloat16(v - __bfloat162float(hi));
        }
    }
}

// ---------------- K0a': fold BN params + biases ----------------
__global__ void packbn_kernel(const float* __restrict__ b1, const float* __restrict__ b2,
                              const float* __restrict__ b3,
                              const float* __restrict__ bn1_g, const float* __restrict__ bn1_b,
                              const float* __restrict__ bn1_m, const float* __restrict__ bn1_v,
                              const float* __restrict__ bn2_g, const float* __restrict__ bn2_b,
                              const float* __restrict__ bn2_m, const float* __restrict__ bn2_v) {
    int c = blockIdx.x * 128 + threadIdx.x;
    if (c >= MID) return;
    g_bias[c] = (c < 32) ? b1[c] : (c < 64) ? b2[c - 32] : b3[c - 64];
    float s = bn1_g[c] * rsqrtf(bn1_v[c] + 1e-5f);
    g_bn1s[c] = s;
    g_bn1b[c] = bn1_b[c] - bn1_m[c] * s;
    if (c < GG) {
        float s2 = bn2_g[c] * rsqrtf(bn2_v[c] + 1e-5f);
        g_bn2s[c] = s2;
        g_bn2b[c] = bn2_b[c] - bn2_m[c] * s2;
    }
}

// ---------------- K0b: transpose + split-convert x -> [b][p][c] bf16 hi/lo ----------------
__global__ __launch_bounds__(256) void xconv_kernel(const float* __restrict__ x) {
    __shared__ float tile[64][33];
    const int b  = blockIdx.z;
    const int c0 = blockIdx.y * 64;
    const int p0 = blockIdx.x * 32;
    const int tid = threadIdx.x;
#pragma unroll
    for (int e = 0; e < 8; e++) {
        int idx = tid + e * 256;
        int c = idx >> 5, j = idx & 31;
        tile[c][j] = x[((size_t)b * CIN + c0 + c) * P + p0 + j];
    }
    __syncthreads();
#pragma unroll
    for (int e = 0; e < 4; e++) {
        int idx = tid + e * 256;
        int p = idx >> 5, cp = idx & 31;
        float f0 = tile[2 * cp][p], f1 = tile[2 * cp + 1][p];
        __nv_bfloat16 h0 = __float2bfloat16(f0);
        __nv_bfloat16 h1 = __float2bfloat16(f1);
        __nv_bfloat16 l0 = __float2bfloat16(f0 - __bfloat162float(h0));
        __nv_bfloat16 l1 = __float2bfloat16(f1 - __bfloat162float(h1));
        size_t off = ((size_t)b * P + p0 + p) * CIN + c0 + 2 * cp;
        *(__nv_bfloat162*)&g_xhi[off] = __nv_bfloat162(h0, h1);
        *(__nv_bfloat162*)&g_xlo[off] = __nv_bfloat162(l0, l1);
    }
}

// ---------------- K1: conv1x1 via mma.sync split-bf16 GEMM, cp.async double-buffered (R7, proven) ---
#define KC 64
#define ST_AHI 0
#define ST_ALO 16384
#define ST_BHI 32768
#define ST_BLO 49152
#define STAGE  65536
#define SM_TOTAL (2 * STAGE)

__global__ __launch_bounds__(256) void conv_mma_kernel() {
    extern __shared__ char smem[];
    const uint32_t sbase = smem_u32(smem);
    const int tid = threadIdx.x;
    const int wid = tid >> 5;
    const int lid = tid & 31;
    const int b  = blockIdx.z;
    const int m0 = blockIdx.y * 128;
    const int p0 = blockIdx.x * 128;
    const int wm = wid & 3;
    const int wn = wid >> 2;

    float acc[2][8][4];
#pragma unroll
    for (int i = 0; i < 2; i++)
#pragma unroll
        for (int j = 0; j < 8; j++)
#pragma unroll
            for (int q = 0; q < 4; q++) acc[i][j][q] = 0.f;

    const int rowA[2] = { wm * 32 + (lid & 15), wm * 32 + 16 + (lid & 15) };
    const int c16A = (lid >> 4) * 16;
    int rowB[4];
#pragma unroll
    for (int nfp = 0; nfp < 4; nfp++)
        rowB[nfp] = wn * 64 + nfp * 16 + ((lid >> 4) * 8) + (lid & 7);
    const int c16B = ((lid >> 3) & 1) * 16;

    const int rowL = tid >> 3;
    const int ccL  = (tid & 7) * 16;

    uint32_t ldst[4];
    const __nv_bfloat16 *srcAh[4], *srcAl[4], *srcBh[4], *srcBl[4];
#pragma unroll
    for (int e = 0; e < 4; e++) {
        int row = rowL + e * 32;
        ldst[e] = (uint32_t)(row * 128) + (uint32_t)(ccL ^ ((row & 7) * 16));
        size_t sA = (size_t)(m0 + row) * CIN + (ccL >> 1);
        size_t sB = ((size_t)b * P + p0 + row) * CIN + (ccL >> 1);
        srcAh[e] = &g_whi[sA]; srcAl[e] = &g_wlo[sA];
        srcBh[e] = &g_xhi[sB]; srcBl[e] = &g_xlo[sB];
    }

    auto issue = [&](int c, int s) {
        const uint32_t stb = sbase + (uint32_t)(s * STAGE);
        const int koff = c * KC;
#pragma unroll
        for (int e = 0; e < 4; e++) {
            CP_ASYNC16(stb + ST_AHI + ldst[e], srcAh[e] + koff);
            CP_ASYNC16(stb + ST_ALO + ldst[e], srcAl[e] + koff);
            CP_ASYNC16(stb + ST_BHI + ldst[e], srcBh[e] + koff);
            CP_ASYNC16(stb + ST_BLO + ldst[e], srcBl[e] + koff);
        }
        CP_COMMIT();
    };

    issue(0, 0);
    for (int c = 0; c < 4; c++) {
        if (c < 3) { issue(c + 1, (c + 1) & 1); CP_WAIT1(); }
        else       { CP_WAIT0(); }
        __syncthreads();

        const uint32_t stb = sbase + (uint32_t)((c & 1) * STAGE);
#pragma unroll
        for (int ks = 0; ks < 4; ks++) {
            const int colA = (ks * 32 + c16A);
            const int colB = (ks * 32 + c16B);
            uint32_t ah[2][4], al[2][4];
#pragma unroll
            for (int mf = 0; mf < 2; mf++) {
                uint32_t off = (uint32_t)(rowA[mf] * 128) +
                               (uint32_t)(colA ^ ((rowA[mf] & 7) * 16));
                LDSM4(ah[mf][0], ah[mf][1], ah[mf][2], ah[mf][3], stb + ST_AHI + off);
                LDSM4(al[mf][0], al[mf][1], al[mf][2], al[mf][3], stb + ST_ALO + off);
            }
            uint32_t bh[8][2], bl[8][2];
#pragma unroll
            for (int nfp = 0; nfp < 4; nfp++) {
                uint32_t off = (uint32_t)(rowB[nfp] * 128) +
                               (uint32_t)(colB ^ ((rowB[nfp] & 7) * 16));
                LDSM4(bh[2 * nfp][0], bh[2 * nfp][1], bh[2 * nfp + 1][0], bh[2 * nfp + 1][1],
                      stb + ST_BHI + off);
                LDSM4(bl[2 * nfp][0], bl[2 * nfp][1], bl[2 * nfp + 1][0], bl[2 * nfp + 1][1],
                      stb + ST_BLO + off);
            }
#pragma unroll
            for (int mf = 0; mf < 2; mf++)
#pragma unroll
                for (int nf = 0; nf < 8; nf++) {
                    MMA_BF16(acc[mf][nf], ah[mf], bh[nf]);
                    MMA_BF16(acc[mf][nf], ah[mf], bl[nf]);
                    MMA_BF16(acc[mf][nf], al[mf], bh[nf]);
                }
        }
        __syncthreads();
    }

    const int r = lid >> 2;
    const int cc = (lid & 3) * 2;
#pragma unroll
    for (int mf = 0; mf < 2; mf++) {
        int m1 = m0 + wm * 32 + mf * 16 + r;
        int m2 = m1 + 8;
        float bv1 = (m1 < MID) ? g_bias[m1] : 0.f;
        float bv2 = (m2 < MID) ? g_bias[m2] : 0.f;
#pragma unroll
        for (int nf = 0; nf < 8; nf++) {
            int p = p0 + wn * 64 + nf * 8 + cc;
            if (m1 < MID) {
                float2 v = make_float2(acc[mf][nf][0] + bv1, acc[mf][nf][1] + bv1);
                *(float2*)&g_y[((size_t)b * MID + m1) * P + p] = v;
            }
            if (m2 < MID) {
                float2 v = make_float2(acc[mf][nf][2] + bv2, acc[mf][nf][3] + bv2);
                *(float2*)&g_y[((size_t)b * MID + m2) * P + p] = v;
            }
        }
    }
}

// ---------------- K3: wgen1 mma — 64 px/CTA, 16x16 warp tiles, 512 CTAs ----------------
#define W1_AH   0
#define W1_AL   20480
#define W1_BH   40960
#define W1_BL   49152
#define W1_C4   57344                       // int4 s_c4[320]
#define W1_CB   (W1_C4 + 320 * 16)          // float s_cb[320]
#define W1_TOTAL (W1_CB + 320 * 4)          // 63744 B

__global__ __launch_bounds__(256) void wgen1_mma_kernel() {
    extern __shared__ char smem[];
    const uint32_t sbase = smem_u32(smem);
    int4*  s_c4 = (int4*)(smem + W1_C4);
    float* s_cb = (float*)(smem + W1_CB);
    const int tid = threadIdx.x;
    const int wid = tid >> 5;
    const int lid = tid & 31;
    const int b  = blockIdx.y;
    const int p0 = blockIdx.x * 64;
    const float* yb = g_y + (size_t)b * MID * P;

    // A tiles (all 5 chunks): [c][32m][64k] swizzled, hi & lo
#pragma unroll
    for (int e = 0; e < 5; e++) {
        int idx = tid + e * 256;
        int c = idx >> 8, rem = idx & 255;
        int m = rem >> 3, kg = rem & 7;
        uint32_t dst = (uint32_t)(c * 4096 + m * 128) + (uint32_t)((kg * 16) ^ ((m & 7) * 16));
        size_t src = (size_t)m * MID + c * 64 + kg * 8;
        *(uint4*)(smem + W1_AH + dst) = *(const uint4*)&g_c1hi[src];
        *(uint4*)(smem + W1_AL + dst) = *(const uint4*)&g_c1lo[src];
    }
    for (int k = tid; k < MID; k += 256) {
        int ch, di, dj;
        if (k < 32) { ch = k; di = 0; dj = 0; }
        else {
            int cc = k - 32;
            int rr = cc / 9, t9 = cc - rr * 9;
            ch = 32 + rr;
            di = t9 / 3 - 1;
            dj = t9 - (t9 / 3) * 3 - 1;
        }
        s_c4[k] = make_int4(ch, di, dj, __float_as_int(g_bn1s[k]));
        s_cb[k] = g_bn1b[k];
    }
    __syncthreads();

    float acc[2][4];
#pragma unroll
    for (int j = 0; j < 2; j++)
#pragma unroll
        for (int q = 0; q < 4; q++) acc[j][q] = 0.f;

    const int wm = wid & 1;             // 2 m-frags of 16 groups
    const int wn = wid >> 1;            // 4 n-quarters of 16 px
    const int rowA = wm * 16 + (lid & 15);
    const int c16A = (lid >> 4) * 16;
    const int rowB = wn * 16 + ((lid >> 4) * 8) + (lid & 7);
    const int c16B = ((lid >> 3) & 1) * 16;

    // fill mapping: 64 px x 64 k; fpx = tid&63, k-quarter = (tid>>6)*16
    const int fpx = tid & 63;
    const int fkh = (tid >> 6) * 16;
    const int pi = (p0 + fpx) >> 6;     // = blockIdx.x (row-aligned)
    const int pj = fpx;

    for (int c = 0; c < 5; c++) {
        const int kk = c * 64;
#pragma unroll
        for (int e = 0; e < 8; e++) {
            int kloc0 = fkh + 2 * e;
            int k0 = kk + kloc0;
            int4 c40 = s_c4[k0];
            int4 c41 = s_c4[k0 + 1];
            float b0 = s_cb[k0], b1 = s_cb[k0 + 1];
            int i0 = pi + c40.y, j0 = pj + c40.z;
            i0 = min(abs(i0), 126 - i0); j0 = min(abs(j0), 126 - j0);
            int i1 = pi + c41.y, j1 = pj + c41.z;
            i1 = min(abs(i1), 126 - i1); j1 = min(abs(j1), 126 - j1);
            float v0 = yb[(size_t)c40.x * P + (i0 << 6) + j0];
            float v1 = yb[(size_t)c41.x * P + (i1 << 6) + j1];
            float h0 = fmaxf(fmaf(v0, __int_as_float(c40.w), b0), 0.f);
            float h1 = fmaxf(fmaf(v1, __int_as_float(c41.w), b1), 0.f);
            __nv_bfloat16 hh0 = __float2bfloat16(h0);
            __nv_bfloat16 hh1 = __float2bfloat16(h1);
            __nv_bfloat16 ll0 = __float2bfloat16(h0 - __bfloat162float(hh0));
            __nv_bfloat16 ll1 = __float2bfloat16(h1 - __bfloat162float(hh1));
            uint32_t dst = (uint32_t)(fpx * 128) + (uint32_t)((kloc0 * 2) ^ ((fpx & 7) * 16));
            *(__nv_bfloat162*)(smem + W1_BH + dst) = __nv_bfloat162(hh0, hh1);
            *(__nv_bfloat162*)(smem + W1_BL + dst) = __nv_bfloat162(ll0, ll1);
        }
        __syncthreads();

        const uint32_t abase = (uint32_t)(c * 4096);
#pragma unroll
        for (int ks = 0; ks < 4; ks++) {
            const int colA = ks * 32 + c16A;
            const int colB = ks * 32 + c16B;
            uint32_t ah[4], al[4];
            {
                uint32_t off = abase + (uint32_t)(rowA * 128) +
                               (uint32_t)(colA ^ ((rowA & 7) * 16));
                LDSM4(ah[0], ah[1], ah[2], ah[3], sbase + W1_AH + off);
                LDSM4(al[0], al[1], al[2], al[3], sbase + W1_AL + off);
            }
            uint32_t bh[2][2], bl[2][2];
            {
                uint32_t off = (uint32_t)(rowB * 128) + (uint32_t)(colB ^ ((rowB & 7) * 16));
                LDSM4(bh[0][0], bh[0][1], bh[1][0], bh[1][1], sbase + W1_BH + off);
                LDSM4(bl[0][0], bl[0][1], bl[1][0], bl[1][1], sbase + W1_BL + off);
            }
#pragma unroll
            for (int nf = 0; nf < 2; nf++) {
                MMA_BF16(acc[nf], ah, bh[nf]);
                MMA_BF16(acc[nf], ah, bl[nf]);
                MMA_BF16(acc[nf], al, bh[nf]);
            }
        }
        __syncthreads();
    }

    // epilogue: bn2 + relu
    const int r = lid >> 2;
    const int c2 = (lid & 3) * 2;
    int g1 = wm * 16 + r;
    int g2 = g1 + 8;
    float s1 = g_bn2s[g1], sb1 = g_bn2b[g1];
    float s2 = g_bn2s[g2], sb2 = g_bn2b[g2];
#pragma unroll
    for (int nf = 0; nf < 2; nf++) {
        int p = p0 + wn * 16 + nf * 8 + c2;
        float2 v1 = make_float2(fmaxf(fmaf(acc[nf][0], s1, sb1), 0.f),
                                fmaxf(fmaf(acc[nf][1], s1, sb1), 0.f));
        *(float2*)&g_t[((size_t)b * GG + g1) * P + p] = v1;
        float2 v2 = make_float2(fmaxf(fmaf(acc[nf][2], s2, sb2), 0.f),
                                fmaxf(fmaf(acc[nf][3], s2, sb2), 0.f));
        *(float2*)&g_t[((size_t)b * GG + g2) * P + p] = v2;
    }
}

// ---------------- K4+K5 fused: per-pixel weight gen + local grouped 3x3 conv ----------------
__global__ __launch_bounds__(256) void wgen2_local_kernel(const float* __restrict__ cw2,
                                                          const float* __restrict__ cb2,
                                                          float* __restrict__ out) {
    __shared__ float ts[GG][64];
    __shared__ float w2s[WOUT * GG];
    __shared__ float cbs[WOUT];
    const int b  = blockIdx.y;
    const int p0 = blockIdx.x * 64;
    const int tid = threadIdx.x;

#pragma unroll
    for (int e = 0; e < 8; e++) {
        int idx = tid + e * 256;
        int g = idx >> 6, n = idx & 63;
        ts[g][n] = g_t[((size_t)b * GG + g) * P + p0 + n];
    }
    for (int idx = tid; idx < WOUT * GG; idx += 256) w2s[idx] = cw2[idx];
    for (int idx = tid; idx < WOUT; idx += 256) cbs[idx] = cb2[idx];
    __syncthreads();

    const int pp = tid & 63;
    const int q  = tid >> 6;
    const int i  = blockIdx.x;
    const int j  = pp;

    float tv[GG];
#pragma unroll
    for (int g = 0; g < GG; g++) tv[g] = ts[g][pp];

#pragma unroll
    for (int g8 = 0; g8 < 8; g8++) {
        const int g = q * 8 + g8;
        float w[9];
#pragma unroll
        for (int t9 = 0; t9 < 9; t9++) {
            float acc = cbs[g * 9 + t9];
            const float4* wrow = (const float4*)&w2s[(g * 9 + t9) * GG];
#pragma unroll
            for (int k4 = 0; k4 < 8; k4++) {
                float4 wv = wrow[k4];
                acc += wv.x * tv[4 * k4] + wv.y * tv[4 * k4 + 1]
                     + wv.z * tv[4 * k4 + 2] + wv.w * tv[4 * k4 + 3];
            }
            w[t9] = acc;
        }
        const float* x3 = g_y + ((size_t)b * MID + 64 + g * SHAREC) * P;
        float* ob = out + ((size_t)b * OUTC + g * SHAREC) * P + p0 + pp;
#pragma unroll
        for (int s = 0; s < SHAREC; s++) {
            const float* xc = x3 + (size_t)s * P;
            float acc = 0.f;
#pragma unroll
            for (int ki = 0; ki < 3; ki++) {
                int ii = i + ki - 1;
                if (ii < 0 || ii > 63) continue;
#pragma unroll
                for (int kj = 0; kj < 3; kj++) {
                    int jj = j + kj - 1;
                    if (jj < 0 || jj > 63) continue;
                    acc += xc[(ii << 6) + jj] * w[ki * 3 + kj];
                }
            }
            ob[(size_t)s * P] = acc;
        }
    }
}

// ---------------- launch ----------------
extern "C" void kernel_launch(void* const* d_in, const int* in_sizes, int n_in,
                              void* d_out, int out_size) {
    const float* x     = (const float*)d_in[0];
    const float* w1    = (const float*)d_in[1];
    const float* b1    = (const float*)d_in[2];
    const float* w2    = (const float*)d_in[3];
    const float* b2    = (const float*)d_in[4];
    const float* w3    = (const float*)d_in[5];
    const float* b3    = (const float*)d_in[6];
    const float* bn1_g = (const float*)d_in[7];
    const float* bn1_b = (const float*)d_in[8];
    const float* bn1_m = (const float*)d_in[9];
    const float* bn1_v = (const float*)d_in[10];
    const float* cw1   = (const float*)d_in[11];
    const float* bn2_g = (const float*)d_in[12];
    const float* bn2_b = (const float*)d_in[13];
    const float* bn2_m = (const float*)d_in[14];
    const float* bn2_v = (const float*)d_in[15];
    const float* cw2   = (const float*)d_in[16];
    const float* cb2   = (const float*)d_in[17];
    float* out = (float*)d_out;

    static int smem_set = 0;
    if (!smem_set) {
        cudaFuncSetAttribute(conv_mma_kernel,
                             cudaFuncAttributeMaxDynamicSharedMemorySize, SM_TOTAL);
        cudaFuncSetAttribute(wgen1_mma_kernel,
                             cudaFuncAttributeMaxDynamicSharedMemorySize, W1_TOTAL);
        smem_set = 1;
    }

    packw_kernel<<<(MIDP * CIN + GG * MID + 255) / 256, 256>>>(w1, w2, w3, cw1);
    packbn_kernel<<<3, 128>>>(b1, b2, b3,
                              bn1_g, bn1_b, bn1_m, bn1_v,
                              bn2_g, bn2_b, bn2_m, bn2_v);
    {
        dim3 grid(P / 32, CIN / 64, BB);      // 128 x 4 x 8
        xconv_kernel<<<grid, 256>>>(x);
    }
    {
        dim3 grid(P / 128, MIDP / 128, BB);   // 32 x 3 x 8
        conv_mma_kernel<<<grid, 256, SM_TOTAL>>>();
    }
    {
        dim3 grid(P / 64, BB);                // 64 x 8
        wgen1_mma_kernel<<<grid, 256, W1_TOTAL>>>();
    }
    {
        dim3 grid(P / 64, BB);                // 64 x 8
        wgen2_local_kernel<<<grid, 256>>>(cw2, cb2, out);
    }
}

// round 10
// speedup vs baseline: 1.0454x; 1.0294x over previous
#include <cuda_runtime.h>
#include <cuda_bf16.h>
#include <math.h>
#include <stdint.h>

#define BB    8
#define CIN   256
#define OUTC  256
#define SHAREC 8
#define GG    32
#define MID   320
#define MIDP  384
#define WOUT  288
#define P     4096

// ---------------- scratch (static device arrays; no allocation) ----------------
__device__ float g_y[(size_t)BB * MID * P];      // conv1x1 outputs [b][c][p]
__device__ float g_t[(size_t)BB * GG * P];       // weight-gen hidden
__device__ float g_bias[MIDP];
__device__ float g_bn1s[MID];
__device__ float g_bn1b[MID];
__device__ float g_bn2s[GG];
__device__ float g_bn2b[GG];
__device__ __nv_bfloat16 g_whi[MIDP * CIN];      // conv weights hi/lo, [m][k]
__device__ __nv_bfloat16 g_wlo[MIDP * CIN];
__device__ __nv_bfloat16 g_xhi[(size_t)BB * P * CIN];  // x transposed: [b][p][c]
__device__ __nv_bfloat16 g_xlo[(size_t)BB * P * CIN];
__device__ __nv_bfloat16 g_c1hi[GG * MID];       // cw1 hi/lo, [g][k]
__device__ __nv_bfloat16 g_c1lo[GG * MID];

__device__ __forceinline__ uint32_t smem_u32(const void* p) {
    uint32_t a;
    asm("{ .reg .u64 t; cvta.to.shared.u64 t, %1; cvt.u32.u64 %0, t; }" : "=r"(a) : "l"(p));
    return a;
}

#define LDSM4(r0, r1, r2, r3, addr) \
    asm volatile("ldmatrix.sync.aligned.m8n8.x4.shared.b16 {%0,%1,%2,%3}, [%4];" \
        : "=r"(r0), "=r"(r1), "=r"(r2), "=r"(r3) : "r"(addr))

#define MMA_BF16(d, a, b) \
    asm volatile("mma.sync.aligned.m16n8k16.row.col.f32.bf16.bf16.f32 " \
        "{%0,%1,%2,%3}, {%4,%5,%6,%7}, {%8,%9}, {%0,%1,%2,%3};" \
        : "+f"((d)[0]), "+f"((d)[1]), "+f"((d)[2]), "+f"((d)[3]) \
        : "r"((a)[0]), "r"((a)[1]), "r"((a)[2]), "r"((a)[3]), "r"((b)[0]), "r"((b)[1]))

#define CP_ASYNC16(saddr, gptr) \
    asm volatile("cp.async.cg.shared.global [%0], [%1], 16;" :: "r"(saddr), "l"(gptr))
#define CP_COMMIT() asm volatile("cp.async.commit_group;" ::: "memory")
#define CP_WAIT1()  asm volatile("cp.async.wait_group 1;" ::: "memory")
#define CP_WAIT0()  asm volatile("cp.async.wait_group 0;" ::: "memory")

// ---------------- K0a: pack + split weights ----------------
__global__ __launch_bounds__(256) void packw_kernel(const float* __restrict__ w1,
                                                    const float* __restrict__ w2,
                                                    const float* __restrict__ w3,
                                                    const float* __restrict__ cw1) {
    int idx = blockIdx.x * 256 + threadIdx.x;
    if (idx < MIDP * CIN) {
        int c = idx >> 8;
        int k = idx & 255;
        float v = 0.f;
        if (c < 32)       v = w1[c * CIN + k];
        else if (c < 64)  v = w2[(c - 32) * CIN + k];
        else if (c < MID) v = w3[(c - 64) * CIN + k];
        __nv_bfloat16 hi = __float2bfloat16(v);
        g_whi[idx] = hi;
        g_wlo[idx] = __float2bfloat16(v - __bfloat162float(hi));
    } else {
        int j = idx - MIDP * CIN;
        if (j < GG * MID) {
            float v = cw1[j];
            __nv_bfloat16 hi = __float2bfloat16(v);
            g_c1hi[j] = hi;
            g_c1lo[j] = __float2bfloat16(v - __bfloat162float(hi));
        }
    }
}

// ---------------- K0a': fold BN params + biases ----------------
__global__ void packbn_kernel(const float* __restrict__ b1, const float* __restrict__ b2,
                              const float* __restrict__ b3,
                              const float* __restrict__ bn1_g, const float* __restrict__ bn1_b,
                              const float* __restrict__ bn1_m, const float* __restrict__ bn1_v,
                              const float* __restrict__ bn2_g, const float* __restrict__ bn2_b,
                              const float* __restrict__ bn2_m, const float* __restrict__ bn2_v) {
    int c = blockIdx.x * 128 + threadIdx.x;
    if (c >= MID) return;
    g_bias[c] = (c < 32) ? b1[c] : (c < 64) ? b2[c - 32] : b3[c - 64];
    float s = bn1_g[c] * rsqrtf(bn1_v[c] + 1e-5f);
    g_bn1s[c] = s;
    g_bn1b[c] = bn1_b[c] - bn1_m[c] * s;
    if (c < GG) {
        float s2 = bn2_g[c] * rsqrtf(bn2_v[c] + 1e-5f);
        g_bn2s[c] = s2;
        g_bn2b[c] = bn2_b[c] - bn2_m[c] * s2;
    }
}

// ---------------- K0b: transpose + split-convert x -> [b][p][c] bf16 hi/lo ----------------
__global__ __launch_bounds__(256) void xconv_kernel(const float* __restrict__ x) {
    __shared__ float tile[64][33];
    const int b  = blockIdx.z;
    const int c0 = blockIdx.y * 64;
    const int p0 = blockIdx.x * 32;
    const int tid = threadIdx.x;
#pragma unroll
    for (int e = 0; e < 8; e++) {
        int idx = tid + e * 256;
        int c = idx >> 5, j = idx & 31;
        tile[c][j] = x[((size_t)b * CIN + c0 + c) * P + p0 + j];
    }
    __syncthreads();
#pragma unroll
    for (int e = 0; e < 4; e++) {
        int idx = tid + e * 256;
        int p = idx >> 5, cp = idx & 31;
        float f0 = tile[2 * cp][p], f1 = tile[2 * cp + 1][p];
        __nv_bfloat16 h0 = __float2bfloat16(f0);
        __nv_bfloat16 h1 = __float2bfloat16(f1);
        __nv_bfloat16 l0 = __float2bfloat16(f0 - __bfloat162float(h0));
        __nv_bfloat16 l1 = __float2bfloat16(f1 - __bfloat162float(h1));
        size_t off = ((size_t)b * P + p0 + p) * CIN + c0 + 2 * cp;
        *(__nv_bfloat162*)&g_xhi[off] = __nv_bfloat162(h0, h1);
        *(__nv_bfloat162*)&g_xlo[off] = __nv_bfloat162(l0, l1);
    }
}

// ---------------- K1: conv1x1 split-bf16 GEMM, M128 x N64 tiles, 2 CTAs/SM ----------------
#define KC 64
#define ST_AHI 0
#define ST_ALO 16384
#define ST_BHI 32768
#define ST_BLO 40960
#define STAGE  49152
#define SM_TOTAL (2 * STAGE)    // 98304

__global__ __launch_bounds__(256, 2) void conv_mma_kernel() {
    extern __shared__ char smem[];
    const uint32_t sbase = smem_u32(smem);
    const int tid = threadIdx.x;
    const int wid = tid >> 5;
    const int lid = tid & 31;
    const int b  = blockIdx.z;
    const int m0 = blockIdx.y * 128;
    const int p0 = blockIdx.x * 64;
    const int wm = wid & 3;      // 4 warps along M (32 m each)
    const int wn = wid >> 2;     // 2 warps along N (32 px each)

    float acc[2][4][4];
#pragma unroll
    for (int i = 0; i < 2; i++)
#pragma unroll
        for (int j = 0; j < 4; j++)
#pragma unroll
            for (int q = 0; q < 4; q++) acc[i][j][q] = 0.f;

    const int rowA[2] = { wm * 32 + (lid & 15), wm * 32 + 16 + (lid & 15) };
    const int c16A = (lid >> 4) * 16;
    int rowB[2];
#pragma unroll
    for (int nfp = 0; nfp < 2; nfp++)
        rowB[nfp] = wn * 32 + nfp * 16 + ((lid >> 4) * 8) + (lid & 7);
    const int c16B = ((lid >> 3) & 1) * 16;

    // loaders: A = 128 rows x 128B (4 rows/thread), B = 64 rows x 128B (2 rows/thread)
    const int rowL = tid >> 3;
    const int ccL  = (tid & 7) * 16;
    uint32_t ldstA[4], ldstB[2];
    const __nv_bfloat16 *srcAh[4], *srcAl[4], *srcBh[2], *srcBl[2];
#pragma unroll
    for (int e = 0; e < 4; e++) {
        int row = rowL + e * 32;
        ldstA[e] = (uint32_t)(row * 128) + (uint32_t)(ccL ^ ((row & 7) * 16));
        size_t sA = (size_t)(m0 + row) * CIN + (ccL >> 1);
        srcAh[e] = &g_whi[sA]; srcAl[e] = &g_wlo[sA];
    }
#pragma unroll
    for (int e = 0; e < 2; e++) {
        int row = rowL + e * 32;
        ldstB[e] = (uint32_t)(row * 128) + (uint32_t)(ccL ^ ((row & 7) * 16));
        size_t sB = ((size_t)b * P + p0 + row) * CIN + (ccL >> 1);
        srcBh[e] = &g_xhi[sB]; srcBl[e] = &g_xlo[sB];
    }

    auto issue = [&](int c, int s) {
        const uint32_t stb = sbase + (uint32_t)(s * STAGE);
        const int koff = c * KC;
#pragma unroll
        for (int e = 0; e < 4; e++) {
            CP_ASYNC16(stb + ST_AHI + ldstA[e], srcAh[e] + koff);
            CP_ASYNC16(stb + ST_ALO + ldstA[e], srcAl[e] + koff);
        }
#pragma unroll
        for (int e = 0; e < 2; e++) {
            CP_ASYNC16(stb + ST_BHI + ldstB[e], srcBh[e] + koff);
            CP_ASYNC16(stb + ST_BLO + ldstB[e], srcBl[e] + koff);
        }
        CP_COMMIT();
    };

    issue(0, 0);
    for (int c = 0; c < 4; c++) {
        if (c < 3) { issue(c + 1, (c + 1) & 1); CP_WAIT1(); }
        else       { CP_WAIT0(); }
        __syncthreads();

        const uint32_t stb = sbase + (uint32_t)((c & 1) * STAGE);
#pragma unroll
        for (int ks = 0; ks < 4; ks++) {
            const int colA = (ks * 32 + c16A);
            const int colB = (ks * 32 + c16B);
            uint32_t ah[2][4], al[2][4];
#pragma unroll
            for (int mf = 0; mf < 2; mf++) {
                uint32_t off = (uint32_t)(rowA[mf] * 128) +
                               (uint32_t)(colA ^ ((rowA[mf] & 7) * 16));
                LDSM4(ah[mf][0], ah[mf][1], ah[mf][2], ah[mf][3], stb + ST_AHI + off);
                LDSM4(al[mf][0], al[mf][1], al[mf][2], al[mf][3], stb + ST_ALO + off);
            }
            uint32_t bh[4][2], bl[4][2];
#pragma unroll
            for (int nfp = 0; nfp < 2; nfp++) {
                uint32_t off = (uint32_t)(rowB[nfp] * 128) +
                               (uint32_t)(colB ^ ((rowB[nfp] & 7) * 16));
                LDSM4(bh[2 * nfp][0], bh[2 * nfp][1], bh[2 * nfp + 1][0], bh[2 * nfp + 1][1],
                      stb + ST_BHI + off);
                LDSM4(bl[2 * nfp][0], bl[2 * nfp][1], bl[2 * nfp + 1][0], bl[2 * nfp + 1][1],
                      stb + ST_BLO + off);
            }
#pragma unroll
            for (int mf = 0; mf < 2; mf++)
#pragma unroll
                for (int nf = 0; nf < 4; nf++) {
                    MMA_BF16(acc[mf][nf], ah[mf], bh[nf]);
                    MMA_BF16(acc[mf][nf], ah[mf], bl[nf]);
                    MMA_BF16(acc[mf][nf], al[mf], bh[nf]);
                }
        }
        __syncthreads();
    }

    const int r = lid >> 2;
    const int cc = (lid & 3) * 2;
#pragma unroll
    for (int mf = 0; mf < 2; mf++) {
        int m1 = m0 + wm * 32 + mf * 16 + r;
        int m2 = m1 + 8;
        float bv1 = (m1 < MID) ? g_bias[m1] : 0.f;
        float bv2 = (m2 < MID) ? g_bias[m2] : 0.f;
#pragma unroll
        for (int nf = 0; nf < 4; nf++) {
            int p = p0 + wn * 32 + nf * 8 + cc;
            if (m1 < MID) {
                float2 v = make_float2(acc[mf][nf][0] + bv1, acc[mf][nf][1] + bv1);
                *(float2*)&g_y[((size_t)b * MID + m1) * P + p] = v;
            }
            if (m2 < MID) {
                float2 v = make_float2(acc[mf][nf][2] + bv2, acc[mf][nf][3] + bv2);
                *(float2*)&g_y[((size_t)b * MID + m2) * P + p] = v;
            }
        }
    }
}

// ---------------- K3: wgen1 via mma.sync, fused reflect-unfold gather (R7 exact, proven) ----------
#define W1_AH   0
#define W1_AL   20480
#define W1_BH   40960
#define W1_BL   57344
#define W1_C4   73728
#define W1_CB   (W1_C4 + 320 * 16)
#define W1_TOTAL (W1_CB + 320 * 4)

__global__ __launch_bounds__(256) void wgen1_mma_kernel() {
    extern __shared__ char smem[];
    const uint32_t sbase = smem_u32(smem);
    int4*  s_c4 = (int4*)(smem + W1_C4);
    float* s_cb = (float*)(smem + W1_CB);
    const int tid = threadIdx.x;
    const int wid = tid >> 5;
    const int lid = tid & 31;
    const int b  = blockIdx.y;
    const int p0 = blockIdx.x * 128;
    const float* yb = g_y + (size_t)b * MID * P;

#pragma unroll
    for (int e = 0; e < 5; e++) {
        int idx = tid + e * 256;
        int c = idx >> 8, rem = idx & 255;
        int m = rem >> 3, kg = rem & 7;
        uint32_t dst = (uint32_t)(c * 4096 + m * 128) + (uint32_t)((kg * 16) ^ ((m & 7) * 16));
        size_t src = (size_t)m * MID + c * 64 + kg * 8;
        *(uint4*)(smem + W1_AH + dst) = *(const uint4*)&g_c1hi[src];
        *(uint4*)(smem + W1_AL + dst) = *(const uint4*)&g_c1lo[src];
    }
    for (int k = tid; k < MID; k += 256) {
        int ch, di, dj;
        if (k < 32) { ch = k; di = 0; dj = 0; }
        else {
            int cc = k - 32;
            int rr = cc / 9, t9 = cc - rr * 9;
            ch = 32 + rr;
            di = t9 / 3 - 1;
            dj = t9 - (t9 / 3) * 3 - 1;
        }
        s_c4[k] = make_int4(ch, di, dj, __float_as_int(g_bn1s[k]));
        s_cb[k] = g_bn1b[k];
    }
    __syncthreads();

    float acc[2][2][4];
#pragma unroll
    for (int i = 0; i < 2; i++)
#pragma unroll
        for (int j = 0; j < 2; j++)
#pragma unroll
            for (int q = 0; q < 4; q++) acc[i][j][q] = 0.f;

    const int rowA[2] = { (lid & 15), 16 + (lid & 15) };
    const int c16A = (lid >> 4) * 16;
    const int rowB = wid * 16 + ((lid >> 4) * 8) + (lid & 7);
    const int c16B = ((lid >> 3) & 1) * 16;

    const int fpx = tid & 127;
    const int fkh = (tid >> 7) * 32;
    const int pi = (p0 + fpx) >> 6;
    const int pj = (p0 + fpx) & 63;

    for (int c = 0; c < 5; c++) {
        const int kk = c * 64;
#pragma unroll
        for (int e = 0; e < 16; e++) {
            int kloc0 = fkh + 2 * e;
            int k0 = kk + kloc0;
            int4 c40 = s_c4[k0];
            int4 c41 = s_c4[k0 + 1];
            float b0 = s_cb[k0], b1 = s_cb[k0 + 1];
            int i0 = pi + c40.y, j0 = pj + c40.z;
            i0 = min(abs(i0), 126 - i0); j0 = min(abs(j0), 126 - j0);
            int i1 = pi + c41.y, j1 = pj + c41.z;
            i1 = min(abs(i1), 126 - i1); j1 = min(abs(j1), 126 - j1);
            float v0 = yb[(size_t)c40.x * P + (i0 << 6) + j0];
            float v1 = yb[(size_t)c41.x * P + (i1 << 6) + j1];
            float h0 = fmaxf(fmaf(v0, __int_as_float(c40.w), b0), 0.f);
            float h1 = fmaxf(fmaf(v1, __int_as_float(c41.w), b1), 0.f);
            __nv_bfloat16 hh0 = __float2bfloat16(h0);
            __nv_bfloat16 hh1 = __float2bfloat16(h1);
            __nv_bfloat16 ll0 = __float2bfloat16(h0 - __bfloat162float(hh0));
            __nv_bfloat16 ll1 = __float2bfloat16(h1 - __bfloat162float(hh1));
            uint32_t dst = (uint32_t)(fpx * 128) + (uint32_t)((kloc0 * 2) ^ ((fpx & 7) * 16));
            *(__nv_bfloat162*)(smem + W1_BH + dst) = __nv_bfloat162(hh0, hh1);
            *(__nv_bfloat162*)(smem + W1_BL + dst) = __nv_bfloat162(ll0, ll1);
        }
        __syncthreads();

        const uint32_t abase = (uint32_t)(c * 4096);
#pragma unroll
        for (int ks = 0; ks < 4; ks++) {
            const int colA = ks * 32 + c16A;
            const int colB = ks * 32 + c16B;
            uint32_t ah[2][4], al[2][4];
#pragma unroll
            for (int mf = 0; mf < 2; mf++) {
                uint32_t off = abase + (uint32_t)(rowA[mf] * 128) +
                               (uint32_t)(colA ^ ((rowA[mf] & 7) * 16));
                LDSM4(ah[mf][0], ah[mf][1], ah[mf][2], ah[mf][3], sbase + W1_AH + off);
                LDSM4(al[mf][0], al[mf][1], al[mf][2], al[mf][3], sbase + W1_AL + off);
            }
            uint32_t bh[2][2], bl[2][2];
            {
                uint32_t off = (uint32_t)(rowB * 128) + (uint32_t)(colB ^ ((rowB & 7) * 16));
                LDSM4(bh[0][0], bh[0][1], bh[1][0], bh[1][1], sbase + W1_BH + off);
                LDSM4(bl[0][0], bl[0][1], bl[1][0], bl[1][1], sbase + W1_BL + off);
            }
#pragma unroll
            for (int mf = 0; mf < 2; mf++)
#pragma unroll
                for (int nf = 0; nf < 2; nf++) {
                    MMA_BF16(acc[mf][nf], ah[mf], bh[nf]);
                    MMA_BF16(acc[mf][nf], ah[mf], bl[nf]);
                    MMA_BF16(acc[mf][nf], al[mf], bh[nf]);
                }
        }
        __syncthreads();
    }

    const int r = lid >> 2;
    const int c2 = (lid & 3) * 2;
#pragma unroll
    for (int mf = 0; mf < 2; mf++) {
        int g1 = mf * 16 + r;
        int g2 = g1 + 8;
        float s1 = g_bn2s[g1], sb1 = g_bn2b[g1];
        float s2 = g_bn2s[g2], sb2 = g_bn2b[g2];
#pragma unroll
        for (int nf = 0; nf < 2; nf++) {
            int p = p0 + wid * 16 + nf * 8 + c2;
            float2 v1 = make_float2(fmaxf(fmaf(acc[mf][nf][0], s1, sb1), 0.f),
                                    fmaxf(fmaf(acc[mf][nf][1], s1, sb1), 0.f));
            *(float2*)&g_t[((size_t)b * GG + g1) * P + p] = v1;
            float2 v2 = make_float2(fmaxf(fmaf(acc[mf][nf][2], s2, sb2), 0.f),
                                    fmaxf(fmaf(acc[mf][nf][3], s2, sb2), 0.f));
            *(float2*)&g_t[((size_t)b * GG + g2) * P + p] = v2;
        }
    }
}

// ---------------- K4+K5 fused: per-pixel weight gen + local grouped 3x3 conv ----------------
__global__ __launch_bounds__(256) void wgen2_local_kernel(const float* __restrict__ cw2,
                                                          const float* __restrict__ cb2,
                                                          float* __restrict__ out) {
    __shared__ float ts[GG][64];
    __shared__ float w2s[WOUT * GG];
    __shared__ float cbs[WOUT];
    const int b  = blockIdx.y;
    const int p0 = blockIdx.x * 64;
    const int tid = threadIdx.x;

#pragma unroll
    for (int e = 0; e < 8; e++) {
        int idx = tid + e * 256;
        int g = idx >> 6, n = idx & 63;
        ts[g][n] = g_t[((size_t)b * GG + g) * P + p0 + n];
    }
    for (int idx = tid; idx < WOUT * GG; idx += 256) w2s[idx] = cw2[idx];
    for (int idx = tid; idx < WOUT; idx += 256) cbs[idx] = cb2[idx];
    __syncthreads();

    const int pp = tid & 63;
    const int q  = tid >> 6;
    const int i  = blockIdx.x;
    const int j  = pp;

    float tv[GG];
#pragma unroll
    for (int g = 0; g < GG; g++) tv[g] = ts[g][pp];

#pragma unroll
    for (int g8 = 0; g8 < 8; g8++) {
        const int g = q * 8 + g8;
        float w[9];
#pragma unroll
        for (int t9 = 0; t9 < 9; t9++) {
            float acc = cbs[g * 9 + t9];
            const float4* wrow = (const float4*)&w2s[(g * 9 + t9) * GG];
#pragma unroll
            for (int k4 = 0; k4 < 8; k4++) {
                float4 wv = wrow[k4];
                acc += wv.x * tv[4 * k4] + wv.y * tv[4 * k4 + 1]
                     + wv.z * tv[4 * k4 + 2] + wv.w * tv[4 * k4 + 3];
            }
            w[t9] = acc;
        }
        const float* x3 = g_y + ((size_t)b * MID + 64 + g * SHAREC) * P;
        float* ob = out + ((size_t)b * OUTC + g * SHAREC) * P + p0 + pp;
#pragma unroll
        for (int s = 0; s < SHAREC; s++) {
            const float* xc = x3 + (size_t)s * P;
            float acc = 0.f;
#pragma unroll
            for (int ki = 0; ki < 3; ki++) {
                int ii = i + ki - 1;
                if (ii < 0 || ii > 63) continue;
#pragma unroll
                for (int kj = 0; kj < 3; kj++) {
                    int jj = j + kj - 1;
                    if (jj < 0 || jj > 63) continue;
                    acc += xc[(ii << 6) + jj] * w[ki * 3 + kj];
                }
            }
            ob[(size_t)s * P] = acc;
        }
    }
}

// ---------------- launch ----------------
extern "C" void kernel_launch(void* const* d_in, const int* in_sizes, int n_in,
                              void* d_out, int out_size) {
    const float* x     = (const float*)d_in[0];
    const float* w1    = (const float*)d_in[1];
    const float* b1    = (const float*)d_in[2];
    const float* w2    = (const float*)d_in[3];
    const float* b2    = (const float*)d_in[4];
    const float* w3    = (const float*)d_in[5];
    const float* b3    = (const float*)d_in[6];
    const float* bn1_g = (const float*)d_in[7];
    const float* bn1_b = (const float*)d_in[8];
    const float* bn1_m = (const float*)d_in[9];
    const float* bn1_v = (const float*)d_in[10];
    const float* cw1   = (const float*)d_in[11];
    const float* bn2_g = (const float*)d_in[12];
    const float* bn2_b = (const float*)d_in[13];
    const float* bn2_m = (const float*)d_in[14];
    const float* bn2_v = (const float*)d_in[15];
    const float* cw2   = (const float*)d_in[16];
    const float* cb2   = (const float*)d_in[17];
    float* out = (float*)d_out;

    static int smem_set = 0;
    if (!smem_set) {
        cudaFuncSetAttribute(conv_mma_kernel,
                             cudaFuncAttributeMaxDynamicSharedMemorySize, SM_TOTAL);
        cudaFuncSetAttribute(wgen1_mma_kernel,
                             cudaFuncAttributeMaxDynamicSharedMemorySize, W1_TOTAL);
        smem_set = 1;
    }

    packw_kernel<<<(MIDP * CIN + GG * MID + 255) / 256, 256>>>(w1, w2, w3, cw1);
    packbn_kernel<<<3, 128>>>(b1, b2, b3,
                              bn1_g, bn1_b, bn1_m, bn1_v,
                              bn2_g, bn2_b, bn2_m, bn2_v);
    {
        dim3 grid(P / 32, CIN / 64, BB);      // 128 x 4 x 8
        xconv_kernel<<<grid, 256>>>(x);
    }
    {
        dim3 grid(P / 64, MIDP / 128, BB);    // 64 x 3 x 8
        conv_mma_kernel<<<grid, 256, SM_TOTAL>>>();
    }
    {
        dim3 grid(P / 128, BB);               // 32 x 8
        wgen1_mma_kernel<<<grid, 256, W1_TOTAL>>>();
    }
    {
        dim3 grid(P / 64, BB);                // 64 x 8
        wgen2_local_kernel<<<grid, 256>>>(cw2, cb2, out);
    }
}

// round 11
// speedup vs baseline: 1.0653x; 1.0190x over previous
#include <cuda_runtime.h>
#include <cuda_bf16.h>
#include <math.h>
#include <stdint.h>

#define BB    8
#define CIN   256
#define OUTC  256
#define SHAREC 8
#define GG    32
#define MID   320
#define MIDP  384
#define WOUT  288
#define P     4096

// ---------------- scratch (static device arrays; no allocation) ----------------
__device__ float g_y[(size_t)BB * MID * P];      // conv1x1 outputs [b][c][p]
__device__ float g_t[(size_t)BB * GG * P];       // weight-gen hidden
__device__ float g_bias[MIDP];
__device__ float g_bn1s[MID];
__device__ float g_bn1b[MID];
__device__ float g_bn2s[GG];
__device__ float g_bn2b[GG];
__device__ __nv_bfloat16 g_whi[MIDP * CIN];      // conv weights hi/lo, [m][k]
__device__ __nv_bfloat16 g_wlo[MIDP * CIN];
__device__ __nv_bfloat16 g_c1hi[GG * MID];       // cw1 hi/lo, [g][k]
__device__ __nv_bfloat16 g_c1lo[GG * MID];

__device__ __forceinline__ uint32_t smem_u32(const void* p) {
    uint32_t a;
    asm("{ .reg .u64 t; cvta.to.shared.u64 t, %1; cvt.u32.u64 %0, t; }" : "=r"(a) : "l"(p));
    return a;
}

#define LDSM4(r0, r1, r2, r3, addr) \
    asm volatile("ldmatrix.sync.aligned.m8n8.x4.shared.b16 {%0,%1,%2,%3}, [%4];" \
        : "=r"(r0), "=r"(r1), "=r"(r2), "=r"(r3) : "r"(addr))

#define MMA_BF16(d, a, b) \
    asm volatile("mma.sync.aligned.m16n8k16.row.col.f32.bf16.bf16.f32 " \
        "{%0,%1,%2,%3}, {%4,%5,%6,%7}, {%8,%9}, {%0,%1,%2,%3};" \
        : "+f"((d)[0]), "+f"((d)[1]), "+f"((d)[2]), "+f"((d)[3]) \
        : "r"((a)[0]), "r"((a)[1]), "r"((a)[2]), "r"((a)[3]), "r"((b)[0]), "r"((b)[1]))

#define CP_ASYNC16(saddr, gptr) \
    asm volatile("cp.async.cg.shared.global [%0], [%1], 16;" :: "r"(saddr), "l"(gptr))
#define CP_COMMIT() asm volatile("cp.async.commit_group;" ::: "memory")
#define CP_WAIT1()  asm volatile("cp.async.wait_group 1;" ::: "memory")
#define CP_WAIT0()  asm volatile("cp.async.wait_group 0;" ::: "memory")

// ---------------- K0a: pack + split weights ----------------
__global__ __launch_bounds__(256) void packw_kernel(const float* __restrict__ w1,
                                                    const float* __restrict__ w2,
                                                    const float* __restrict__ w3,
                                                    const float* __restrict__ cw1) {
    int idx = blockIdx.x * 256 + threadIdx.x;
    if (idx < MIDP * CIN) {
        int c = idx >> 8;
        int k = idx & 255;
        float v = 0.f;
        if (c < 32)       v = w1[c * CIN + k];
        else if (c < 64)  v = w2[(c - 32) * CIN + k];
        else if (c < MID) v = w3[(c - 64) * CIN + k];
        __nv_bfloat16 hi = __float2bfloat16(v);
        g_whi[idx] = hi;
        g_wlo[idx] = __float2bfloat16(v - __bfloat162float(hi));
    } else {
        int j = idx - MIDP * CIN;
        if (j < GG * MID) {
            float v = cw1[j];
            __nv_bfloat16 hi = __float2bfloat16(v);
            g_c1hi[j] = hi;
            g_c1lo[j] = __float2bfloat16(v - __bfloat162float(hi));
        }
    }
}

// ---------------- K0a': fold BN params + biases ----------------
__global__ void packbn_kernel(const float* __restrict__ b1, const float* __restrict__ b2,
                              const float* __restrict__ b3,
                              const float* __restrict__ bn1_g, const float* __restrict__ bn1_b,
                              const float* __restrict__ bn1_m, const float* __restrict__ bn1_v,
                              const float* __restrict__ bn2_g, const float* __restrict__ bn2_b,
                              const float* __restrict__ bn2_m, const float* __restrict__ bn2_v) {
    int c = blockIdx.x * 128 + threadIdx.x;
    if (c >= MID) return;
    g_bias[c] = (c < 32) ? b1[c] : (c < 64) ? b2[c - 32] : b3[c - 64];
    float s = bn1_g[c] * rsqrtf(bn1_v[c] + 1e-5f);
    g_bn1s[c] = s;
    g_bn1b[c] = bn1_b[c] - bn1_m[c] * s;
    if (c < GG) {
        float s2 = bn2_g[c] * rsqrtf(bn2_v[c] + 1e-5f);
        g_bn2s[c] = s2;
        g_bn2b[c] = bn2_b[c] - bn2_m[c] * s2;
    }
}

// ---------------- K1: conv1x1 split-bf16 GEMM, M128 x N64, fused x convert, 2 CTAs/SM ----------
// A (weights bf16 hi/lo) + raw fp32 x tile cp.async double-buffered;
// x converted in-kernel to single-buffered swizzled [px][k] bf16 hi/lo B tile.
#define KC 64
#define ST_AHI 0
#define ST_ALO 16384
#define ST_X   32768          // fp32 staging: 64 k-rows x 64 px x 4B = 16 KB
#define STAGE  49152
#define CB_HI  98304          // converted B: 64 px rows x 128 B
#define CB_LO  106496
#define SM_TOTAL 114688

__global__ __launch_bounds__(256, 2) void conv_mma_kernel(const float* __restrict__ x) {
    extern __shared__ char smem[];
    const uint32_t sbase = smem_u32(smem);
    const int tid = threadIdx.x;
    const int wid = tid >> 5;
    const int lid = tid & 31;
    const int b  = blockIdx.z;
    const int m0 = blockIdx.y * 128;
    const int p0 = blockIdx.x * 64;
    const int wm = wid & 3;      // 4 warps along M (32 m each)
    const int wn = wid >> 2;     // 2 warps along N (32 px each)

    float acc[2][4][4];
#pragma unroll
    for (int i = 0; i < 2; i++)
#pragma unroll
        for (int j = 0; j < 4; j++)
#pragma unroll
            for (int q = 0; q < 4; q++) acc[i][j][q] = 0.f;

    const int rowA[2] = { wm * 32 + (lid & 15), wm * 32 + 16 + (lid & 15) };
    const int c16A = (lid >> 4) * 16;
    int rowB[2];
#pragma unroll
    for (int nfp = 0; nfp < 2; nfp++)
        rowB[nfp] = wn * 32 + nfp * 16 + ((lid >> 4) * 8) + (lid & 7);
    const int c16B = ((lid >> 3) & 1) * 16;

    // A loader: 128 rows x 128B, 4 rows per thread
    const int rowL = tid >> 3;
    const int ccL  = (tid & 7) * 16;
    uint32_t ldstA[4];
    const __nv_bfloat16 *srcAh[4], *srcAl[4];
#pragma unroll
    for (int e = 0; e < 4; e++) {
        int row = rowL + e * 32;
        ldstA[e] = (uint32_t)(row * 128) + (uint32_t)(ccL ^ ((row & 7) * 16));
        size_t sA = (size_t)(m0 + row) * CIN + (ccL >> 1);
        srcAh[e] = &g_whi[sA]; srcAl[e] = &g_wlo[sA];
    }
    // X loader: 64 k-rows x 256B = 1024 x 16B chunks, 4 per thread
    const float* xbase = x + (size_t)b * CIN * P + p0;
    const int kxL = tid >> 4;          // 16 threads per k-row
    const int uxL = (tid & 15) * 16;   // byte col within 256B row

    auto issue = [&](int c, int s) {
        const uint32_t stb = sbase + (uint32_t)(s * STAGE);
        const int koff = c * KC;
#pragma unroll
        for (int e = 0; e < 4; e++) {
            CP_ASYNC16(stb + ST_AHI + ldstA[e], srcAh[e] + koff);
            CP_ASYNC16(stb + ST_ALO + ldstA[e], srcAl[e] + koff);
        }
#pragma unroll
        for (int e = 0; e < 4; e++) {
            int kx = kxL + e * 16;
            CP_ASYNC16(stb + ST_X + (uint32_t)(kx * 256) + (uint32_t)uxL,
                       xbase + (size_t)(koff + kx) * P + (uxL >> 2));
        }
        CP_COMMIT();
    };

    // convert mapping: px = tid&63, k-quarter = (tid>>6)*16
    const int cvp = tid & 63;
    const int cvk = (tid >> 6) * 16;

    issue(0, 0);
    for (int c = 0; c < 4; c++) {
        if (c < 3) { issue(c + 1, (c + 1) & 1); CP_WAIT1(); }
        else       { CP_WAIT0(); }
        __syncthreads();    // stage c landed; previous MMA retired (bottom sync)

        // ---- convert fp32 X staging -> swizzled bf16 hi/lo B tile (single-buffered) ----
        {
            const char* xs = smem + (c & 1) * STAGE + ST_X;
#pragma unroll
            for (int e = 0; e < 8; e++) {
                int k = cvk + 2 * e;
                float f0 = *(const float*)(xs + k * 256 + cvp * 4);
                float f1 = *(const float*)(xs + (k + 1) * 256 + cvp * 4);
                __nv_bfloat16 h0 = __float2bfloat16(f0);
                __nv_bfloat16 h1 = __float2bfloat16(f1);
                __nv_bfloat16 l0 = __float2bfloat16(f0 - __bfloat162float(h0));
                __nv_bfloat16 l1 = __float2bfloat16(f1 - __bfloat162float(h1));
                uint32_t d = (uint32_t)(cvp * 128) + (uint32_t)((2 * k) ^ ((cvp & 7) * 16));
                *(__nv_bfloat162*)(smem + CB_HI + d) = __nv_bfloat162(h0, h1);
                *(__nv_bfloat162*)(smem + CB_LO + d) = __nv_bfloat162(l0, l1);
            }
        }
        __syncthreads();    // B tile ready

        const uint32_t stb = sbase + (uint32_t)((c & 1) * STAGE);
#pragma unroll
        for (int ks = 0; ks < 4; ks++) {
            const int colA = (ks * 32 + c16A);
            const int colB = (ks * 32 + c16B);
            uint32_t ah[2][4], al[2][4];
#pragma unroll
            for (int mf = 0; mf < 2; mf++) {
                uint32_t off = (uint32_t)(rowA[mf] * 128) +
                               (uint32_t)(colA ^ ((rowA[mf] & 7) * 16));
                LDSM4(ah[mf][0], ah[mf][1], ah[mf][2], ah[mf][3], stb + ST_AHI + off);
                LDSM4(al[mf][0], al[mf][1], al[mf][2], al[mf][3], stb + ST_ALO + off);
            }
            uint32_t bh[4][2], bl[4][2];
#pragma unroll
            for (int nfp = 0; nfp < 2; nfp++) {
                uint32_t off = (uint32_t)(rowB[nfp] * 128) +
                               (uint32_t)(colB ^ ((rowB[nfp] & 7) * 16));
                LDSM4(bh[2 * nfp][0], bh[2 * nfp][1], bh[2 * nfp + 1][0], bh[2 * nfp + 1][1],
                      sbase + CB_HI + off);
                LDSM4(bl[2 * nfp][0], bl[2 * nfp][1], bl[2 * nfp + 1][0], bl[2 * nfp + 1][1],
                      sbase + CB_LO + off);
            }
#pragma unroll
            for (int mf = 0; mf < 2; mf++)
#pragma unroll
                for (int nf = 0; nf < 4; nf++) {
                    MMA_BF16(acc[mf][nf], ah[mf], bh[nf]);
                    MMA_BF16(acc[mf][nf], ah[mf], bl[nf]);
                    MMA_BF16(acc[mf][nf], al[mf], bh[nf]);
                }
        }
        __syncthreads();    // retire stage-c readers + B readers before next issue/convert
    }

    const int r = lid >> 2;
    const int cc = (lid & 3) * 2;
#pragma unroll
    for (int mf = 0; mf < 2; mf++) {
        int m1 = m0 + wm * 32 + mf * 16 + r;
        int m2 = m1 + 8;
        float bv1 = (m1 < MID) ? g_bias[m1] : 0.f;
        float bv2 = (m2 < MID) ? g_bias[m2] : 0.f;
#pragma unroll
        for (int nf = 0; nf < 4; nf++) {
            int p = p0 + wn * 32 + nf * 8 + cc;
            if (m1 < MID) {
                float2 v = make_float2(acc[mf][nf][0] + bv1, acc[mf][nf][1] + bv1);
                *(float2*)&g_y[((size_t)b * MID + m1) * P + p] = v;
            }
            if (m2 < MID) {
                float2 v = make_float2(acc[mf][nf][2] + bv2, acc[mf][nf][3] + bv2);
                *(float2*)&g_y[((size_t)b * MID + m2) * P + p] = v;
            }
        }
    }
}

// ---------------- K3: wgen1 via mma.sync, fused reflect-unfold gather (R7 exact, proven) ----------
#define W1_AH   0
#define W1_AL   20480
#define W1_BH   40960
#define W1_BL   57344
#define W1_C4   73728
#define W1_CB   (W1_C4 + 320 * 16)
#define W1_TOTAL (W1_CB + 320 * 4)

__global__ __launch_bounds__(256) void wgen1_mma_kernel() {
    extern __shared__ char smem[];
    const uint32_t sbase = smem_u32(smem);
    int4*  s_c4 = (int4*)(smem + W1_C4);
    float* s_cb = (float*)(smem + W1_CB);
    const int tid = threadIdx.x;
    const int wid = tid >> 5;
    const int lid = tid & 31;
    const int b  = blockIdx.y;
    const int p0 = blockIdx.x * 128;
    const float* yb = g_y + (size_t)b * MID * P;

#pragma unroll
    for (int e = 0; e < 5; e++) {
        int idx = tid + e * 256;
        int c = idx >> 8, rem = idx & 255;
        int m = rem >> 3, kg = rem & 7;
        uint32_t dst = (uint32_t)(c * 4096 + m * 128) + (uint32_t)((kg * 16) ^ ((m & 7) * 16));
        size_t src = (size_t)m * MID + c * 64 + kg * 8;
        *(uint4*)(smem + W1_AH + dst) = *(const uint4*)&g_c1hi[src];
        *(uint4*)(smem + W1_AL + dst) = *(const uint4*)&g_c1lo[src];
    }
    for (int k = tid; k < MID; k += 256) {
        int ch, di, dj;
        if (k < 32) { ch = k; di = 0; dj = 0; }
        else {
            int cc = k - 32;
            int rr = cc / 9, t9 = cc - rr * 9;
            ch = 32 + rr;
            di = t9 / 3 - 1;
            dj = t9 - (t9 / 3) * 3 - 1;
        }
        s_c4[k] = make_int4(ch, di, dj, __float_as_int(g_bn1s[k]));
        s_cb[k] = g_bn1b[k];
    }
    __syncthreads();

    float acc[2][2][4];
#pragma unroll
    for (int i = 0; i < 2; i++)
#pragma unroll
        for (int j = 0; j < 2; j++)
#pragma unroll
            for (int q = 0; q < 4; q++) acc[i][j][q] = 0.f;

    const int rowA[2] = { (lid & 15), 16 + (lid & 15) };
    const int c16A = (lid >> 4) * 16;
    const int rowB = wid * 16 + ((lid >> 4) * 8) + (lid & 7);
    const int c16B = ((lid >> 3) & 1) * 16;

    const int fpx = tid & 127;
    const int fkh = (tid >> 7) * 32;
    const int pi = (p0 + fpx) >> 6;
    const int pj = (p0 + fpx) & 63;

    for (int c = 0; c < 5; c++) {
        const int kk = c * 64;
#pragma unroll
        for (int e = 0; e < 16; e++) {
            int kloc0 = fkh + 2 * e;
            int k0 = kk + kloc0;
            int4 c40 = s_c4[k0];
            int4 c41 = s_c4[k0 + 1];
            float b0 = s_cb[k0], b1 = s_cb[k0 + 1];
            int i0 = pi + c40.y, j0 = pj + c40.z;
            i0 = min(abs(i0), 126 - i0); j0 = min(abs(j0), 126 - j0);
            int i1 = pi + c41.y, j1 = pj + c41.z;
            i1 = min(abs(i1), 126 - i1); j1 = min(abs(j1), 126 - j1);
            float v0 = yb[(size_t)c40.x * P + (i0 << 6) + j0];
            float v1 = yb[(size_t)c41.x * P + (i1 << 6) + j1];
            float h0 = fmaxf(fmaf(v0, __int_as_float(c40.w), b0), 0.f);
            float h1 = fmaxf(fmaf(v1, __int_as_float(c41.w), b1), 0.f);
            __nv_bfloat16 hh0 = __float2bfloat16(h0);
            __nv_bfloat16 hh1 = __float2bfloat16(h1);
            __nv_bfloat16 ll0 = __float2bfloat16(h0 - __bfloat162float(hh0));
            __nv_bfloat16 ll1 = __float2bfloat16(h1 - __bfloat162float(hh1));
            uint32_t dst = (uint32_t)(fpx * 128) + (uint32_t)((kloc0 * 2) ^ ((fpx & 7) * 16));
            *(__nv_bfloat162*)(smem + W1_BH + dst) = __nv_bfloat162(hh0, hh1);
            *(__nv_bfloat162*)(smem + W1_BL + dst) = __nv_bfloat162(ll0, ll1);
        }
        __syncthreads();

        const uint32_t abase = (uint32_t)(c * 4096);
#pragma unroll
        for (int ks = 0; ks < 4; ks++) {
            const int colA = ks * 32 + c16A;
            const int colB = ks * 32 + c16B;
            uint32_t ah[2][4], al[2][4];
#pragma unroll
            for (int mf = 0; mf < 2; mf++) {
                uint32_t off = abase + (uint32_t)(rowA[mf] * 128) +
                               (uint32_t)(colA ^ ((rowA[mf] & 7) * 16));
                LDSM4(ah[mf][0], ah[mf][1], ah[mf][2], ah[mf][3], sbase + W1_AH + off);
                LDSM4(al[mf][0], al[mf][1], al[mf][2], al[mf][3], sbase + W1_AL + off);
            }
            uint32_t bh[2][2], bl[2][2];
            {
                uint32_t off = (uint32_t)(rowB * 128) + (uint32_t)(colB ^ ((rowB & 7) * 16));
                LDSM4(bh[0][0], bh[0][1], bh[1][0], bh[1][1], sbase + W1_BH + off);
                LDSM4(bl[0][0], bl[0][1], bl[1][0], bl[1][1], sbase + W1_BL + off);
            }
#pragma unroll
            for (int mf = 0; mf < 2; mf++)
#pragma unroll
                for (int nf = 0; nf < 2; nf++) {
                    MMA_BF16(acc[mf][nf], ah[mf], bh[nf]);
                    MMA_BF16(acc[mf][nf], ah[mf], bl[nf]);
                    MMA_BF16(acc[mf][nf], al[mf], bh[nf]);
                }
        }
        __syncthreads();
    }

    const int r = lid >> 2;
    const int c2 = (lid & 3) * 2;
#pragma unroll
    for (int mf = 0; mf < 2; mf++) {
        int g1 = mf * 16 + r;
        int g2 = g1 + 8;
        float s1 = g_bn2s[g1], sb1 = g_bn2b[g1];
        float s2 = g_bn2s[g2], sb2 = g_bn2b[g2];
#pragma unroll
        for (int nf = 0; nf < 2; nf++) {
            int p = p0 + wid * 16 + nf * 8 + c2;
            float2 v1 = make_float2(fmaxf(fmaf(acc[mf][nf][0], s1, sb1), 0.f),
                                    fmaxf(fmaf(acc[mf][nf][1], s1, sb1), 0.f));
            *(float2*)&g_t[((size_t)b * GG + g1) * P + p] = v1;
            float2 v2 = make_float2(fmaxf(fmaf(acc[mf][nf][2], s2, sb2), 0.f),
                                    fmaxf(fmaf(acc[mf][nf][3], s2, sb2), 0.f));
            *(float2*)&g_t[((size_t)b * GG + g2) * P + p] = v2;
        }
    }
}

// ---------------- K4+K5 fused: per-pixel weight gen + local grouped 3x3 conv ----------------
__global__ __launch_bounds__(256) void wgen2_local_kernel(const float* __restrict__ cw2,
                                                          const float* __restrict__ cb2,
                                                          float* __restrict__ out) {
    __shared__ float ts[GG][64];
    __shared__ float w2s[WOUT * GG];
    __shared__ float cbs[WOUT];
    const int b  = blockIdx.y;
    const int p0 = blockIdx.x * 64;
    const int tid = threadIdx.x;

#pragma unroll
    for (int e = 0; e < 8; e++) {
        int idx = tid + e * 256;
        int g = idx >> 6, n = idx & 63;
        ts[g][n] = g_t[((size_t)b * GG + g) * P + p0 + n];
    }
    for (int idx = tid; idx < WOUT * GG; idx += 256) w2s[idx] = cw2[idx];
    for (int idx = tid; idx < WOUT; idx += 256) cbs[idx] = cb2[idx];
    __syncthreads();

    const int pp = tid & 63;
    const int q  = tid >> 6;
    const int i  = blockIdx.x;
    const int j  = pp;

    float tv[GG];
#pragma unroll
    for (int g = 0; g < GG; g++) tv[g] = ts[g][pp];

#pragma unroll
    for (int g8 = 0; g8 < 8; g8++) {
        const int g = q * 8 + g8;
        float w[9];
#pragma unroll
        for (int t9 = 0; t9 < 9; t9++) {
            float acc = cbs[g * 9 + t9];
            const float4* wrow = (const float4*)&w2s[(g * 9 + t9) * GG];
#pragma unroll
            for (int k4 = 0; k4 < 8; k4++) {
                float4 wv = wrow[k4];
                acc += wv.x * tv[4 * k4] + wv.y * tv[4 * k4 + 1]
                     + wv.z * tv[4 * k4 + 2] + wv.w * tv[4 * k4 + 3];
            }
            w[t9] = acc;
        }
        const float* x3 = g_y + ((size_t)b * MID + 64 + g * SHAREC) * P;
        float* ob = out + ((size_t)b * OUTC + g * SHAREC) * P + p0 + pp;
#pragma unroll
        for (int s = 0; s < SHAREC; s++) {
            const float* xc = x3 + (size_t)s * P;
            float acc = 0.f;
#pragma unroll
            for (int ki = 0; ki < 3; ki++) {
                int ii = i + ki - 1;
                if (ii < 0 || ii > 63) continue;
#pragma unroll
                for (int kj = 0; kj < 3; kj++) {
                    int jj = j + kj - 1;
                    if (jj < 0 || jj > 63) continue;
                    acc += xc[(ii << 6) + jj] * w[ki * 3 + kj];
                }
            }
            ob[(size_t)s * P] = acc;
        }
    }
}

// ---------------- launch ----------------
extern "C" void kernel_launch(void* const* d_in, const int* in_sizes, int n_in,
                              void* d_out, int out_size) {
    const float* x     = (const float*)d_in[0];
    const float* w1    = (const float*)d_in[1];
    const float* b1    = (const float*)d_in[2];
    const float* w2    = (const float*)d_in[3];
    const float* b2    = (const float*)d_in[4];
    const float* w3    = (const float*)d_in[5];
    const float* b3    = (const float*)d_in[6];
    const float* bn1_g = (const float*)d_in[7];
    const float* bn1_b = (const float*)d_in[8];
    const float* bn1_m = (const float*)d_in[9];
    const float* bn1_v = (const float*)d_in[10];
    const float* cw1   = (const float*)d_in[11];
    const float* bn2_g = (const float*)d_in[12];
    const float* bn2_b = (const float*)d_in[13];
    const float* bn2_m = (const float*)d_in[14];
    const float* bn2_v = (const float*)d_in[15];
    const float* cw2   = (const float*)d_in[16];
    const float* cb2   = (const float*)d_in[17];
    float* out = (float*)d_out;

    static int smem_set = 0;
    if (!smem_set) {
        cudaFuncSetAttribute(conv_mma_kernel,
                             cudaFuncAttributeMaxDynamicSharedMemorySize, SM_TOTAL);
        cudaFuncSetAttribute(wgen1_mma_kernel,
                             cudaFuncAttributeMaxDynamicSharedMemorySize, W1_TOTAL);
        smem_set = 1;
    }

    packw_kernel<<<(MIDP * CIN + GG * MID + 255) / 256, 256>>>(w1, w2, w3, cw1);
    packbn_kernel<<<3, 128>>>(b1, b2, b3,
                              bn1_g, bn1_b, bn1_m, bn1_v,
                              bn2_g, bn2_b, bn2_m, bn2_v);
    {
        dim3 grid(P / 64, MIDP / 128, BB);    // 64 x 3 x 8
        conv_mma_kernel<<<grid, 256, SM_TOTAL>>>(x);
    }
    {
        dim3 grid(P / 128, BB);               // 32 x 8
        wgen1_mma_kernel<<<grid, 256, W1_TOTAL>>>();
    }
    {
        dim3 grid(P / 64, BB);                // 64 x 8
        wgen2_local_kernel<<<grid, 256>>>(cw2, cb2, out);
    }
}